// round 16
// baseline (speedup 1.0000x reference)
#include <cuda_runtime.h>
#include <cuda_fp16.h>
#include <cstdint>

// ============================ configuration ============================
// 128 CTAs (one wave), 256 threads (8 warps = 4 independent 2-warp units).
// Unit u owns rows [32u, 32u+32); warp w of the unit owns N-half [128w, 128w+128).
// Own-half A fragments live in registers (packed D identity); partner half via smem.
// Rotated loop: own+aug MMAs of step t+1 issue BEFORE the publish barriers, so the
// barrier/STS window is hidden under independent tensor work.
#define NUM_CTAS 128
#define THREADS  256
#define T_STEPS  79
#define TCOLS    79

// B-fragment region, PAIRED layout: [kt 0..16][ntp 0..15][lane][4x u32] = 17*16*512 B
#define SMEM_BFRAG   0
#define BFRAG_BYTES  (17 * 16 * 512)
// A(h)-fragment region: [mt_g 0..7][kt 0..15][lane][4x u32] = 8*16*512 B
#define SMEM_HFRAG   BFRAG_BYTES
#define HFRAG_BYTES  (8 * 16 * 512)
#define SMEM_TOTAL   (BFRAG_BYTES + HFRAG_BYTES)   // 204800 B

// ============================ helpers ============================
static __device__ __forceinline__ uint32_t pk(float lo, float hi) {
    uint32_t r;
    asm("cvt.rn.f16x2.f32 %0, %1, %2;" : "=r"(r) : "f"(hi), "f"(lo));
    return r;
}
static __device__ __forceinline__ uint32_t pkrelu(float lo, float hi) {
    uint32_t r;
    asm("cvt.rn.relu.f16x2.f32 %0, %1, %2;" : "=r"(r) : "f"(hi), "f"(lo));
    return r;
}
static __device__ __forceinline__ float f16hi(float v) {
    return __half2float(__float2half_rn(v));
}

#define MMA16816(c, a, b) \
    asm volatile("mma.sync.aligned.m16n8k16.row.col.f32.f16.f16.f32 " \
        "{%0,%1,%2,%3}, {%4,%5,%6,%7}, {%8,%9}, {%0,%1,%2,%3};" \
        : "+f"((c)[0]), "+f"((c)[1]), "+f"((c)[2]), "+f"((c)[3]) \
        : "r"((a).x), "r"((a).y), "r"((a).z), "r"((a).w), "r"((b).x), "r"((b).y))

#define UNIT_BAR(u) asm volatile("bar.sync %0, 64;" :: "r"(1 + (u)) : "memory")

// paired B-fragment slot (16B per lane): kt 0..16, ntp 0..15
static __device__ __forceinline__ uint32_t bpair_off(int kt, int ntp, int lane) {
    return SMEM_BFRAG + (uint32_t)((kt * 16 + ntp) << 9) + (uint32_t)(lane << 4);
}
static __device__ __forceinline__ uint32_t hfrag_off(int mt_g, int kt, int lane) {
    return SMEM_HFRAG + (uint32_t)((mt_g * 16 + kt) << 9) + (uint32_t)(lane << 4);
}

// ---- build B fragments (paired layout) from row-major fp32 M[256][256] ----
static __device__ __forceinline__ void fill_B_frags(char* smem, const float* __restrict__ M, int lo) {
    const int lane = threadIdx.x & 31;
    const int w    = threadIdx.x >> 5;
    const int n_in = (lane >> 2);
    const int kof  = (lane & 3) * 2;
    for (int s = w; s < 512; s += 8) {                // kt 0..15, nt 0..31
        const int kt = s >> 5, nt = s & 31;
        const int k0 = kt * 16 + kof;
        const int n  = nt * 8 + n_in;
        float v00 = __ldg(M + (k0    ) * 256 + n);
        float v01 = __ldg(M + (k0 + 1) * 256 + n);
        float v10 = __ldg(M + (k0 + 8) * 256 + n);
        float v11 = __ldg(M + (k0 + 9) * 256 + n);
        if (lo) {
            v00 -= f16hi(v00); v01 -= f16hi(v01);
            v10 -= f16hi(v10); v11 -= f16hi(v11);
        }
        uint2 b;
        b.x = pk(v00, v01);
        b.y = pk(v10, v11);
        *reinterpret_cast<uint2*>(smem + bpair_off(kt, nt >> 1, lane) + ((nt & 1) << 3)) = b;
    }
}

// aug B row: k0..2 = Wh, k3..5 = Wl, k6..8 = Wh, k9 = b_rnn, else 0
static __device__ __forceinline__ float baug_val(int k, int n,
                                                const float* __restrict__ W_in,
                                                const float* __restrict__ b_rnn) {
    if (k < 3)  return f16hi(__ldg(W_in + k * 256 + n));
    if (k < 6)  { float v = __ldg(W_in + (k - 3) * 256 + n); return v - f16hi(v); }
    if (k < 9)  return f16hi(__ldg(W_in + (k - 6) * 256 + n));
    if (k == 9) return __ldg(b_rnn + n);
    return 0.0f;
}

// aug A slot: k0..2 = xh, k3..5 = xh, k6..8 = xl, k9 = 1, else 0.
// sum = xh*Wh + xh*Wl + xl*Wh + b = x*W + b - xl*Wl (|xl*Wl| < 1e-7)
static __device__ __forceinline__ float aaug_val(int k, float xh0, float xh1, float xh2,
                                                 float xl0, float xl1, float xl2) {
    switch (k) {
        case 0: return xh0;  case 1: return xh1;  case 2: return xh2;
        case 3: return xh0;  case 4: return xh1;  case 5: return xh2;
        case 6: return xl0;  case 7: return xl1;  case 8: return xl2;
        case 9: return 1.0f;
        default: return 0.0f;
    }
}

// build one aug-A fragment in registers from 6 x-values (rows p=r0, q=r0+8)
static __device__ __forceinline__ uint4 make_augA(int kof,
                                                  float p0, float p1, float p2,
                                                  float q0, float q1, float q2) {
    float ph0 = f16hi(p0), ph1 = f16hi(p1), ph2 = f16hi(p2);
    float qh0 = f16hi(q0), qh1 = f16hi(q1), qh2 = f16hi(q2);
    float pl0 = p0 - ph0, pl1 = p1 - ph1, pl2 = p2 - ph2;
    float ql0 = q0 - qh0, ql1 = q1 - qh1, ql2 = q2 - qh2;
    uint4 a;
    a.x = pk(aaug_val(kof,     ph0, ph1, ph2, pl0, pl1, pl2),
             aaug_val(kof + 1, ph0, ph1, ph2, pl0, pl1, pl2));
    a.y = pk(aaug_val(kof,     qh0, qh1, qh2, ql0, ql1, ql2),
             aaug_val(kof + 1, qh0, qh1, qh2, ql0, ql1, ql2));
    a.z = pk(aaug_val(kof + 8, ph0, ph1, ph2, pl0, pl1, pl2),
             aaug_val(kof + 9, ph0, ph1, ph2, pl0, pl1, pl2));
    a.w = pk(aaug_val(kof + 8, qh0, qh1, qh2, ql0, ql1, ql2),
             aaug_val(kof + 9, qh0, qh1, qh2, ql0, ql1, ql2));
    return a;
}

// ============================ kernel ============================
__global__ void __launch_bounds__(THREADS, 1)
rnn_hmma_kernel(const float* __restrict__ x0, const float* __restrict__ x1,
                const float* __restrict__ x2, const float* __restrict__ W_in,
                const float* __restrict__ U,  const float* __restrict__ b_rnn,
                const float* __restrict__ W_d, const float* __restrict__ b_d,
                float* __restrict__ out)
{
    extern __shared__ __align__(128) char smem[];
    const int tid  = threadIdx.x;
    const int lane = tid & 31;
    const int wid  = tid >> 5;
    const int u    = wid >> 1;          // unit 0..3 (owns 32 rows)
    const int w    = wid & 1;           // N-half 0/1 (128 cols)
    const int rowBase = blockIdx.x * 128;
    const int unitRow = rowBase + u * 32;
    const int ntp0 = w * 8;             // paired B slot base for this warp

    // -------- init: U -> B frags; aug B staged at kt=16 --------
    fill_B_frags(smem, U, 0);
    {
        const int n_in = (lane >> 2);
        const int kof  = (lane & 3) * 2;
        for (int s = 512 + wid; s < 544; s += 8) {
            const int nt = s & 31;
            const int n  = nt * 8 + n_in;
            uint2 b;
            b.x = pk(baug_val(kof,     n, W_in, b_rnn), baug_val(kof + 1, n, W_in, b_rnn));
            b.y = pk(baug_val(kof + 8, n, W_in, b_rnn), baug_val(kof + 9, n, W_in, b_rnn));
            *reinterpret_cast<uint2*>(smem + bpair_off(16, nt >> 1, lane) + ((nt & 1) << 3)) = b;
        }
    }
    __syncthreads();

    // x addressing: mt 0..1, rows p = unitRow + 16mt + lane/4, q = p + 8
    const int aug_kof = (lane & 3) * 2;
    int xg0[2], xg1[2];
#pragma unroll
    for (int mt = 0; mt < 2; ++mt) {
        int r0 = unitRow + mt * 16 + (lane >> 2);
        xg0[mt] = r0 * TCOLS;
        xg1[mt] = (r0 + 8) * TCOLS;
    }

    // aug A fragments for step 0 (original time col 78)
    uint4 augA[2];
#pragma unroll
    for (int mt = 0; mt < 2; ++mt) {
        const int tc = 78;
        augA[mt] = make_augA(aug_kof,
            __ldg(x0 + xg0[mt] + tc), __ldg(x1 + xg0[mt] + tc), __ldg(x2 + xg0[mt] + tc),
            __ldg(x0 + xg1[mt] + tc), __ldg(x1 + xg1[mt] + tc), __ldg(x2 + xg1[mt] + tc));
    }

    uint4 a_own[2][8];                  // own-half packed h (kt = 8w + ktl)
    const int fbase = 8 * (1 - w);
    const int obase = 8 * w;

    float c[2][16][4];
#pragma unroll
    for (int mt = 0; mt < 2; ++mt)
#pragma unroll
        for (int nt = 0; nt < 16; ++nt)
#pragma unroll
            for (int i = 0; i < 4; ++i) c[mt][nt][i] = 0.0f;

    // ---- prologue: aug MMAs for step 0 (h0 == 0, so this is the full step-0 sum) ----
#pragma unroll
    for (int half = 0; half < 2; ++half) {
        uint2 b8[8];
#pragma unroll
        for (int q = 0; q < 4; ++q) {
            uint4 bb = *reinterpret_cast<const uint4*>(
                smem + bpair_off(16, ntp0 + half * 4 + q, lane));
            b8[2 * q]     = make_uint2(bb.x, bb.y);
            b8[2 * q + 1] = make_uint2(bb.z, bb.w);
        }
#pragma unroll
        for (int mt = 0; mt < 2; ++mt)
#pragma unroll
            for (int j = 0; j < 8; ++j)
                MMA16816(c[mt][half * 8 + j], augA[mt], b8[j]);
    }

    // ============================ 79 recurrent steps (rotated) ============================
    // Loop-top invariant: c holds own+aug contributions for step t; h(t) frags published.
#pragma unroll 1
    for (int t = 0; t < T_STEPS; ++t) {
        // ---- prefetch next step's x early (L2-resident; consumed after pack) ----
        float px[2][3], qx[2][3];
        if (t < T_STEPS - 1) {
            const int tc = 77 - t;
#pragma unroll
            for (int mt = 0; mt < 2; ++mt) {
                px[mt][0] = __ldg(x0 + xg0[mt] + tc);
                px[mt][1] = __ldg(x1 + xg0[mt] + tc);
                px[mt][2] = __ldg(x2 + xg0[mt] + tc);
                qx[mt][0] = __ldg(x0 + xg1[mt] + tc);
                qx[mt][1] = __ldg(x1 + xg1[mt] + tc);
                qx[mt][2] = __ldg(x2 + xg1[mt] + tc);
            }
        }

        // ---- foreign kts of step t (A from partner's published frags) ----
        if (t) {
#pragma unroll
            for (int fk = 0; fk < 8; ++fk) {
                const int kt = fbase + fk;
                uint4 a[2];
#pragma unroll
                for (int mt = 0; mt < 2; ++mt)
                    a[mt] = *reinterpret_cast<const uint4*>(smem + hfrag_off(2 * u + mt, kt, lane));
#pragma unroll
                for (int half = 0; half < 2; ++half) {
                    uint2 b8[8];
#pragma unroll
                    for (int q = 0; q < 4; ++q) {
                        uint4 bb = *reinterpret_cast<const uint4*>(
                            smem + bpair_off(kt, ntp0 + half * 4 + q, lane));
                        b8[2 * q]     = make_uint2(bb.x, bb.y);
                        b8[2 * q + 1] = make_uint2(bb.z, bb.w);
                    }
#pragma unroll
                    for (int mt = 0; mt < 2; ++mt)
#pragma unroll
                        for (int j = 0; j < 8; ++j)
                            MMA16816(c[mt][half * 8 + j], a[mt], b8[j]);
                }
            }
        }

        // ---- pack h(t+1) = relu(D) into registers (no smem yet) ----
#pragma unroll
        for (int mt = 0; mt < 2; ++mt) {
#pragma unroll
            for (int ktl = 0; ktl < 8; ++ktl) {
                uint4 hq;
                hq.x = pkrelu(c[mt][2 * ktl][0],     c[mt][2 * ktl][1]);
                hq.y = pkrelu(c[mt][2 * ktl][2],     c[mt][2 * ktl][3]);
                hq.z = pkrelu(c[mt][2 * ktl + 1][0], c[mt][2 * ktl + 1][1]);
                hq.w = pkrelu(c[mt][2 * ktl + 1][2], c[mt][2 * ktl + 1][3]);
                a_own[mt][ktl] = hq;
            }
        }

        if (t < T_STEPS - 1) {
            // build augA(t+1) and zero c
#pragma unroll
            for (int mt = 0; mt < 2; ++mt)
                augA[mt] = make_augA(aug_kof,
                    px[mt][0], px[mt][1], px[mt][2],
                    qx[mt][0], qx[mt][1], qx[mt][2]);
#pragma unroll
            for (int mt = 0; mt < 2; ++mt)
#pragma unroll
                for (int nt = 0; nt < 16; ++nt)
#pragma unroll
                    for (int i = 0; i < 4; ++i) c[mt][nt][i] = 0.0f;

            // ---- own kts of step t+1 (A in regs) — independent of partner ----
#pragma unroll
            for (int ok = 0; ok < 8; ++ok) {
                const int kt = obase + ok;
#pragma unroll
                for (int half = 0; half < 2; ++half) {
                    uint2 b8[8];
#pragma unroll
                    for (int q = 0; q < 4; ++q) {
                        uint4 bb = *reinterpret_cast<const uint4*>(
                            smem + bpair_off(kt, ntp0 + half * 4 + q, lane));
                        b8[2 * q]     = make_uint2(bb.x, bb.y);
                        b8[2 * q + 1] = make_uint2(bb.z, bb.w);
                    }
#pragma unroll
                    for (int mt = 0; mt < 2; ++mt)
#pragma unroll
                        for (int j = 0; j < 8; ++j)
                            MMA16816(c[mt][half * 8 + j], a_own[mt][ok], b8[j]);
                }
            }

            // ---- aug kt of step t+1 ----
#pragma unroll
            for (int half = 0; half < 2; ++half) {
                uint2 b8[8];
#pragma unroll
                for (int q = 0; q < 4; ++q) {
                    uint4 bb = *reinterpret_cast<const uint4*>(
                        smem + bpair_off(16, ntp0 + half * 4 + q, lane));
                    b8[2 * q]     = make_uint2(bb.x, bb.y);
                    b8[2 * q + 1] = make_uint2(bb.z, bb.w);
                }
#pragma unroll
                for (int mt = 0; mt < 2; ++mt)
#pragma unroll
                    for (int j = 0; j < 8; ++j)
                        MMA16816(c[mt][half * 8 + j], augA[mt], b8[j]);
            }
        }

        // ---- publish h(t+1): partner's step-t reads done, then STS, then visible ----
        UNIT_BAR(u);
#pragma unroll
        for (int mt = 0; mt < 2; ++mt)
#pragma unroll
            for (int ktl = 0; ktl < 8; ++ktl)
                *reinterpret_cast<uint4*>(smem + hfrag_off(2 * u + mt, obase + ktl, lane))
                    = a_own[mt][ktl];
        UNIT_BAR(u);
    }

    __syncthreads();   // all units done; full hT is in smem

    // ============================ final: out = hT @ W_d + b_d ============================
    {
        const int wm = wid >> 2;
        const int wn = wid & 3;
        float cf[4][8][4];
#pragma unroll
        for (int mt = 0; mt < 4; ++mt)
#pragma unroll
            for (int nt = 0; nt < 8; ++nt)
#pragma unroll
                for (int i = 0; i < 4; ++i) cf[mt][nt][i] = 0.0f;

#pragma unroll 1
        for (int pass = 0; pass < 2; ++pass) {
            fill_B_frags(smem, W_d, pass);
            __syncthreads();
#pragma unroll
            for (int kt = 0; kt < 16; ++kt) {
                uint4 a[4];
#pragma unroll
                for (int mt = 0; mt < 4; ++mt)
                    a[mt] = *reinterpret_cast<const uint4*>(smem + hfrag_off(wm * 4 + mt, kt, lane));
                uint2 b[8];
#pragma unroll
                for (int ntp = 0; ntp < 4; ++ntp) {
                    uint4 bb = *reinterpret_cast<const uint4*>(smem + bpair_off(kt, wn * 4 + ntp, lane));
                    b[2 * ntp]     = make_uint2(bb.x, bb.y);
                    b[2 * ntp + 1] = make_uint2(bb.z, bb.w);
                }
#pragma unroll
                for (int mt = 0; mt < 4; ++mt)
#pragma unroll
                    for (int nt = 0; nt < 8; ++nt)
                        MMA16816(cf[mt][nt], a[mt], b[nt]);
            }
            __syncthreads();   // this pass's B reads done before refill
        }

        // ---- store: out[row][col] = D + b_d ----
        const int cb_base = wn * 64 + (lane & 3) * 2;
        float2 bdv[8];
#pragma unroll
        for (int nt = 0; nt < 8; ++nt)
            bdv[nt] = *reinterpret_cast<const float2*>(b_d + cb_base + nt * 8);

        const int r_base = rowBase + wm * 64 + (lane >> 2);
#pragma unroll
        for (int mt = 0; mt < 4; ++mt) {
            const size_t r0 = (size_t)(r_base + mt * 16) * 256;
            const size_t r1 = r0 + 8 * 256;
#pragma unroll
            for (int nt = 0; nt < 8; ++nt) {
                const int cb = cb_base + nt * 8;
                float2 v0, v1;
                v0.x = cf[mt][nt][0] + bdv[nt].x;
                v0.y = cf[mt][nt][1] + bdv[nt].y;
                v1.x = cf[mt][nt][2] + bdv[nt].x;
                v1.y = cf[mt][nt][3] + bdv[nt].y;
                *reinterpret_cast<float2*>(out + r0 + cb) = v0;
                *reinterpret_cast<float2*>(out + r1 + cb) = v1;
            }
        }
    }
}

// ============================ launch ============================
extern "C" void kernel_launch(void* const* d_in, const int* in_sizes, int n_in,
                              void* d_out, int out_size) {
    (void)in_sizes; (void)n_in; (void)out_size;
    cudaFuncSetAttribute(rnn_hmma_kernel,
                         cudaFuncAttributeMaxDynamicSharedMemorySize, SMEM_TOTAL);
    rnn_hmma_kernel<<<NUM_CTAS, THREADS, SMEM_TOTAL>>>(
        (const float*)d_in[0], (const float*)d_in[1], (const float*)d_in[2],
        (const float*)d_in[3], (const float*)d_in[4], (const float*)d_in[5],
        (const float*)d_in[6], (const float*)d_in[7],
        (float*)d_out);
}

// round 17
// speedup vs baseline: 1.0347x; 1.0347x over previous
#include <cuda_runtime.h>
#include <cuda_fp16.h>
#include <cstdint>

// ============================ configuration ============================
// 128 CTAs (one wave), 256 threads (8 warps = 4 independent 2-warp units).
// Unit u owns rows [32u, 32u+32); warp w of the unit owns N-half [128w, 128w+128).
// Own-half A fragments live in registers (packed D identity); partner half via smem.
// Units 2,3 delayed ~half a step via clock spin to anti-phase SMSP warp pairs.
#define NUM_CTAS 128
#define THREADS  256
#define T_STEPS  79
#define TCOLS    79
#define SKEW_CYC 5000u

// B-fragment region, PAIRED layout: [kt 0..16][ntp 0..15][lane][4x u32] = 17*16*512 B
#define SMEM_BFRAG   0
#define BFRAG_BYTES  (17 * 16 * 512)
// A(h)-fragment region: [mt_g 0..7][kt 0..15][lane][4x u32] = 8*16*512 B
#define SMEM_HFRAG   BFRAG_BYTES
#define HFRAG_BYTES  (8 * 16 * 512)
#define SMEM_TOTAL   (BFRAG_BYTES + HFRAG_BYTES)   // 204800 B

// ============================ helpers ============================
static __device__ __forceinline__ uint32_t pk(float lo, float hi) {
    uint32_t r;
    asm("cvt.rn.f16x2.f32 %0, %1, %2;" : "=r"(r) : "f"(hi), "f"(lo));
    return r;
}
static __device__ __forceinline__ uint32_t pkrelu(float lo, float hi) {
    uint32_t r;
    asm("cvt.rn.relu.f16x2.f32 %0, %1, %2;" : "=r"(r) : "f"(hi), "f"(lo));
    return r;
}
static __device__ __forceinline__ float f16hi(float v) {
    return __half2float(__float2half_rn(v));
}

#define MMA16816(c, a, b) \
    asm volatile("mma.sync.aligned.m16n8k16.row.col.f32.f16.f16.f32 " \
        "{%0,%1,%2,%3}, {%4,%5,%6,%7}, {%8,%9}, {%0,%1,%2,%3};" \
        : "+f"((c)[0]), "+f"((c)[1]), "+f"((c)[2]), "+f"((c)[3]) \
        : "r"((a).x), "r"((a).y), "r"((a).z), "r"((a).w), "r"((b).x), "r"((b).y))

// first-touch variant: C input is a zero register; overwrites c (saves zeroing MOVs)
#define MMA16816_Z(c, a, b) \
    asm volatile("mma.sync.aligned.m16n8k16.row.col.f32.f16.f16.f32 " \
        "{%0,%1,%2,%3}, {%4,%5,%6,%7}, {%8,%9}, {%10,%10,%10,%10};" \
        : "=f"((c)[0]), "=f"((c)[1]), "=f"((c)[2]), "=f"((c)[3]) \
        : "r"((a).x), "r"((a).y), "r"((a).z), "r"((a).w), "r"((b).x), "r"((b).y), \
          "f"(0.0f))

#define UNIT_BAR(u) asm volatile("bar.sync %0, 64;" :: "r"(1 + (u)) : "memory")

// paired B-fragment slot (16B per lane): kt 0..16, ntp 0..15
static __device__ __forceinline__ uint32_t bpair_off(int kt, int ntp, int lane) {
    return SMEM_BFRAG + (uint32_t)((kt * 16 + ntp) << 9) + (uint32_t)(lane << 4);
}
static __device__ __forceinline__ uint32_t hfrag_off(int mt_g, int kt, int lane) {
    return SMEM_HFRAG + (uint32_t)((mt_g * 16 + kt) << 9) + (uint32_t)(lane << 4);
}

// ---- build B fragments (paired layout) from row-major fp32 M[256][256] ----
static __device__ __forceinline__ void fill_B_frags(char* smem, const float* __restrict__ M, int lo) {
    const int lane = threadIdx.x & 31;
    const int w    = threadIdx.x >> 5;
    const int n_in = (lane >> 2);
    const int kof  = (lane & 3) * 2;
    for (int s = w; s < 512; s += 8) {                // kt 0..15, nt 0..31
        const int kt = s >> 5, nt = s & 31;
        const int k0 = kt * 16 + kof;
        const int n  = nt * 8 + n_in;
        float v00 = __ldg(M + (k0    ) * 256 + n);
        float v01 = __ldg(M + (k0 + 1) * 256 + n);
        float v10 = __ldg(M + (k0 + 8) * 256 + n);
        float v11 = __ldg(M + (k0 + 9) * 256 + n);
        if (lo) {
            v00 -= f16hi(v00); v01 -= f16hi(v01);
            v10 -= f16hi(v10); v11 -= f16hi(v11);
        }
        uint2 b;
        b.x = pk(v00, v01);
        b.y = pk(v10, v11);
        *reinterpret_cast<uint2*>(smem + bpair_off(kt, nt >> 1, lane) + ((nt & 1) << 3)) = b;
    }
}

// aug B row: k0..2 = Wh, k3..5 = Wl, k6..8 = Wh, k9 = b_rnn, else 0
static __device__ __forceinline__ float baug_val(int k, int n,
                                                const float* __restrict__ W_in,
                                                const float* __restrict__ b_rnn) {
    if (k < 3)  return f16hi(__ldg(W_in + k * 256 + n));
    if (k < 6)  { float v = __ldg(W_in + (k - 3) * 256 + n); return v - f16hi(v); }
    if (k < 9)  return f16hi(__ldg(W_in + (k - 6) * 256 + n));
    if (k == 9) return __ldg(b_rnn + n);
    return 0.0f;
}

// aug A slot: k0..2 = xh, k3..5 = xh, k6..8 = xl, k9 = 1, else 0.
// sum = xh*Wh + xh*Wl + xl*Wh + b = x*W + b - xl*Wl (|xl*Wl| < 1e-7)
static __device__ __forceinline__ float aaug_val(int k, float xh0, float xh1, float xh2,
                                                 float xl0, float xl1, float xl2) {
    switch (k) {
        case 0: return xh0;  case 1: return xh1;  case 2: return xh2;
        case 3: return xh0;  case 4: return xh1;  case 5: return xh2;
        case 6: return xl0;  case 7: return xl1;  case 8: return xl2;
        case 9: return 1.0f;
        default: return 0.0f;
    }
}

// build one aug-A fragment in registers from 6 x-values (rows p=r0, q=r0+8)
static __device__ __forceinline__ uint4 make_augA(int kof,
                                                  float p0, float p1, float p2,
                                                  float q0, float q1, float q2) {
    float ph0 = f16hi(p0), ph1 = f16hi(p1), ph2 = f16hi(p2);
    float qh0 = f16hi(q0), qh1 = f16hi(q1), qh2 = f16hi(q2);
    float pl0 = p0 - ph0, pl1 = p1 - ph1, pl2 = p2 - ph2;
    float ql0 = q0 - qh0, ql1 = q1 - qh1, ql2 = q2 - qh2;
    uint4 a;
    a.x = pk(aaug_val(kof,     ph0, ph1, ph2, pl0, pl1, pl2),
             aaug_val(kof + 1, ph0, ph1, ph2, pl0, pl1, pl2));
    a.y = pk(aaug_val(kof,     qh0, qh1, qh2, ql0, ql1, ql2),
             aaug_val(kof + 1, qh0, qh1, qh2, ql0, ql1, ql2));
    a.z = pk(aaug_val(kof + 8, ph0, ph1, ph2, pl0, pl1, pl2),
             aaug_val(kof + 9, ph0, ph1, ph2, pl0, pl1, pl2));
    a.w = pk(aaug_val(kof + 8, qh0, qh1, qh2, ql0, ql1, ql2),
             aaug_val(kof + 9, qh0, qh1, qh2, ql0, ql1, ql2));
    return a;
}

// ============================ kernel ============================
__global__ void __launch_bounds__(THREADS, 1)
rnn_hmma_kernel(const float* __restrict__ x0, const float* __restrict__ x1,
                const float* __restrict__ x2, const float* __restrict__ W_in,
                const float* __restrict__ U,  const float* __restrict__ b_rnn,
                const float* __restrict__ W_d, const float* __restrict__ b_d,
                float* __restrict__ out)
{
    extern __shared__ __align__(128) char smem[];
    const int tid  = threadIdx.x;
    const int lane = tid & 31;
    const int wid  = tid >> 5;
    const int u    = wid >> 1;          // unit 0..3 (owns 32 rows)
    const int w    = wid & 1;           // N-half 0/1 (128 cols)
    const int rowBase = blockIdx.x * 128;
    const int unitRow = rowBase + u * 32;
    const int ntp0 = w * 8;             // paired B slot base for this warp

    // -------- init: U -> B frags; aug B staged at kt=16 --------
    fill_B_frags(smem, U, 0);
    {
        const int n_in = (lane >> 2);
        const int kof  = (lane & 3) * 2;
        for (int s = 512 + wid; s < 544; s += 8) {
            const int nt = s & 31;
            const int n  = nt * 8 + n_in;
            uint2 b;
            b.x = pk(baug_val(kof,     n, W_in, b_rnn), baug_val(kof + 1, n, W_in, b_rnn));
            b.y = pk(baug_val(kof + 8, n, W_in, b_rnn), baug_val(kof + 9, n, W_in, b_rnn));
            *reinterpret_cast<uint2*>(smem + bpair_off(16, nt >> 1, lane) + ((nt & 1) << 3)) = b;
        }
    }
    __syncthreads();

    // x addressing: mt 0..1, rows p = unitRow + 16mt + lane/4, q = p + 8
    const int aug_kof = (lane & 3) * 2;
    int xg0[2], xg1[2];
#pragma unroll
    for (int mt = 0; mt < 2; ++mt) {
        int r0 = unitRow + mt * 16 + (lane >> 2);
        xg0[mt] = r0 * TCOLS;
        xg1[mt] = (r0 + 8) * TCOLS;
    }

    // aug A fragments for step 0 (original time col 78)
    uint4 augA[2];
#pragma unroll
    for (int mt = 0; mt < 2; ++mt) {
        const int tc = 78;
        augA[mt] = make_augA(aug_kof,
            __ldg(x0 + xg0[mt] + tc), __ldg(x1 + xg0[mt] + tc), __ldg(x2 + xg0[mt] + tc),
            __ldg(x0 + xg1[mt] + tc), __ldg(x1 + xg1[mt] + tc), __ldg(x2 + xg1[mt] + tc));
    }

    // ---- true phase skew: delay units 2,3 by ~half a step so SMSP-co-resident
    //      warp pairs (u0/u2, u1/u3) run anti-phase ----
    if (u >= 2) {
        uint32_t t0 = (uint32_t)clock();
        while ((uint32_t)clock() - t0 < SKEW_CYC) { }
    }

    // own-half packed h (A fragments for global kt = 8w + ktl), valid from t>=1
    uint4 a_own[2][8];
    const int fbase = 8 * (1 - w);
    const int obase = 8 * w;

    // ============================ 79 recurrent steps ============================
    float c[2][16][4];

#pragma unroll 1
    for (int t = 0; t < T_STEPS; ++t) {
        // ---- main K work: own kts (A in regs, ok==0 overwrites c), aug, foreign ----
        if (t) {
#pragma unroll
            for (int ok = 0; ok < 8; ++ok) {
                const int kt = obase + ok;
#pragma unroll
                for (int half = 0; half < 2; ++half) {
                    uint2 b8[8];
#pragma unroll
                    for (int q = 0; q < 4; ++q) {
                        uint4 bb = *reinterpret_cast<const uint4*>(
                            smem + bpair_off(kt, ntp0 + half * 4 + q, lane));
                        b8[2 * q]     = make_uint2(bb.x, bb.y);
                        b8[2 * q + 1] = make_uint2(bb.z, bb.w);
                    }
                    if (ok == 0) {
#pragma unroll
                        for (int mt = 0; mt < 2; ++mt)
#pragma unroll
                            for (int j = 0; j < 8; ++j)
                                MMA16816_Z(c[mt][half * 8 + j], a_own[mt][0], b8[j]);
                    } else {
#pragma unroll
                        for (int mt = 0; mt < 2; ++mt)
#pragma unroll
                            for (int j = 0; j < 8; ++j)
                                MMA16816(c[mt][half * 8 + j], a_own[mt][ok], b8[j]);
                    }
                }
            }
        }

        // ---- aug k-tile (kt = 16); first touch of c when t == 0 ----
#pragma unroll
        for (int half = 0; half < 2; ++half) {
            uint2 b8[8];
#pragma unroll
            for (int q = 0; q < 4; ++q) {
                uint4 bb = *reinterpret_cast<const uint4*>(
                    smem + bpair_off(16, ntp0 + half * 4 + q, lane));
                b8[2 * q]     = make_uint2(bb.x, bb.y);
                b8[2 * q + 1] = make_uint2(bb.z, bb.w);
            }
            if (t == 0) {
#pragma unroll
                for (int mt = 0; mt < 2; ++mt)
#pragma unroll
                    for (int j = 0; j < 8; ++j)
                        MMA16816_Z(c[mt][half * 8 + j], augA[mt], b8[j]);
            } else {
#pragma unroll
                for (int mt = 0; mt < 2; ++mt)
#pragma unroll
                    for (int j = 0; j < 8; ++j)
                        MMA16816(c[mt][half * 8 + j], augA[mt], b8[j]);
            }
        }

        // ---- prefetch next step's x (L2-resident) ----
        float px[2][3], qx[2][3];
        if (t < T_STEPS - 1) {
            const int tc = 77 - t;
#pragma unroll
            for (int mt = 0; mt < 2; ++mt) {
                px[mt][0] = __ldg(x0 + xg0[mt] + tc);
                px[mt][1] = __ldg(x1 + xg0[mt] + tc);
                px[mt][2] = __ldg(x2 + xg0[mt] + tc);
                qx[mt][0] = __ldg(x0 + xg1[mt] + tc);
                qx[mt][1] = __ldg(x1 + xg1[mt] + tc);
                qx[mt][2] = __ldg(x2 + xg1[mt] + tc);
            }
        }

        // ---- foreign kts (A from partner's smem fragments) ----
        if (t) {
#pragma unroll
            for (int fk = 0; fk < 8; ++fk) {
                const int kt = fbase + fk;
                uint4 a[2];
#pragma unroll
                for (int mt = 0; mt < 2; ++mt)
                    a[mt] = *reinterpret_cast<const uint4*>(smem + hfrag_off(2 * u + mt, kt, lane));
#pragma unroll
                for (int half = 0; half < 2; ++half) {
                    uint2 b8[8];
#pragma unroll
                    for (int q = 0; q < 4; ++q) {
                        uint4 bb = *reinterpret_cast<const uint4*>(
                            smem + bpair_off(kt, ntp0 + half * 4 + q, lane));
                        b8[2 * q]     = make_uint2(bb.x, bb.y);
                        b8[2 * q + 1] = make_uint2(bb.z, bb.w);
                    }
#pragma unroll
                    for (int mt = 0; mt < 2; ++mt)
#pragma unroll
                        for (int j = 0; j < 8; ++j)
                            MMA16816(c[mt][half * 8 + j], a[mt], b8[j]);
                }
            }
        }

        // ---- rebuild aug A for step t+1 (register-only; overlaps MMA drain) ----
        if (t < T_STEPS - 1) {
#pragma unroll
            for (int mt = 0; mt < 2; ++mt)
                augA[mt] = make_augA(aug_kof,
                    px[mt][0], px[mt][1], px[mt][2],
                    qx[mt][0], qx[mt][1], qx[mt][2]);
        }

        UNIT_BAR(u);   // partner's reads of our previous fragments complete

        // ---- epilogue: pack h(t+1) = relu(D) into a_own (regs) + STS for partner ----
#pragma unroll
        for (int mt = 0; mt < 2; ++mt) {
#pragma unroll
            for (int ktl = 0; ktl < 8; ++ktl) {
                uint4 hq;
                hq.x = pkrelu(c[mt][2 * ktl][0],     c[mt][2 * ktl][1]);
                hq.y = pkrelu(c[mt][2 * ktl][2],     c[mt][2 * ktl][3]);
                hq.z = pkrelu(c[mt][2 * ktl + 1][0], c[mt][2 * ktl + 1][1]);
                hq.w = pkrelu(c[mt][2 * ktl + 1][2], c[mt][2 * ktl + 1][3]);
                a_own[mt][ktl] = hq;
                *reinterpret_cast<uint4*>(smem + hfrag_off(2 * u + mt, obase + ktl, lane)) = hq;
            }
        }

        UNIT_BAR(u);   // our fragments visible to partner
    }

    __syncthreads();   // all units done; full hT is in smem

    // ============================ final: out = hT @ W_d + b_d ============================
    // Single fp16 pass (W_d hi only): output-layer quant ~2.4e-4, no recurrence gain.
    {
        const int wm = wid >> 2;
        const int wn = wid & 3;
        float cf[4][8][4];

        fill_B_frags(smem, W_d, 0);
        __syncthreads();
#pragma unroll
        for (int kt = 0; kt < 16; ++kt) {
            uint4 a[4];
#pragma unroll
            for (int mt = 0; mt < 4; ++mt)
                a[mt] = *reinterpret_cast<const uint4*>(smem + hfrag_off(wm * 4 + mt, kt, lane));
            uint2 b[8];
#pragma unroll
            for (int ntp = 0; ntp < 4; ++ntp) {
                uint4 bb = *reinterpret_cast<const uint4*>(smem + bpair_off(kt, wn * 4 + ntp, lane));
                b[2 * ntp]     = make_uint2(bb.x, bb.y);
                b[2 * ntp + 1] = make_uint2(bb.z, bb.w);
            }
            if (kt == 0) {
#pragma unroll
                for (int mt = 0; mt < 4; ++mt)
#pragma unroll
                    for (int nt = 0; nt < 8; ++nt)
                        MMA16816_Z(cf[mt][nt], a[mt], b[nt]);
            } else {
#pragma unroll
                for (int mt = 0; mt < 4; ++mt)
#pragma unroll
                    for (int nt = 0; nt < 8; ++nt)
                        MMA16816(cf[mt][nt], a[mt], b[nt]);
            }
        }

        // ---- store: out[row][col] = D + b_d ----
        const int cb_base = wn * 64 + (lane & 3) * 2;
        float2 bdv[8];
#pragma unroll
        for (int nt = 0; nt < 8; ++nt)
            bdv[nt] = *reinterpret_cast<const float2*>(b_d + cb_base + nt * 8);

        const int r_base = rowBase + wm * 64 + (lane >> 2);
#pragma unroll
        for (int mt = 0; mt < 4; ++mt) {
            const size_t r0 = (size_t)(r_base + mt * 16) * 256;
            const size_t r1 = r0 + 8 * 256;
#pragma unroll
            for (int nt = 0; nt < 8; ++nt) {
                const int cb = cb_base + nt * 8;
                float2 v0, v1;
                v0.x = cf[mt][nt][0] + bdv[nt].x;
                v0.y = cf[mt][nt][1] + bdv[nt].y;
                v1.x = cf[mt][nt][2] + bdv[nt].x;
                v1.y = cf[mt][nt][3] + bdv[nt].y;
                *reinterpret_cast<float2*>(out + r0 + cb) = v0;
                *reinterpret_cast<float2*>(out + r1 + cb) = v1;
            }
        }
    }
}

// ============================ launch ============================
extern "C" void kernel_launch(void* const* d_in, const int* in_sizes, int n_in,
                              void* d_out, int out_size) {
    (void)in_sizes; (void)n_in; (void)out_size;
    cudaFuncSetAttribute(rnn_hmma_kernel,
                         cudaFuncAttributeMaxDynamicSharedMemorySize, SMEM_TOTAL);
    rnn_hmma_kernel<<<NUM_CTAS, THREADS, SMEM_TOTAL>>>(
        (const float*)d_in[0], (const float*)d_in[1], (const float*)d_in[2],
        (const float*)d_in[3], (const float*)d_in[4], (const float*)d_in[5],
        (const float*)d_in[6], (const float*)d_in[7],
        (float*)d_out);
}